// round 10
// baseline (speedup 1.0000x reference)
#include <cuda_runtime.h>
#include <cuda_bf16.h>

#define BB 4
#define NN 10000
#define MM 10000
#define PP 128
#define KS 32
#define ZF 128
#define HALVES 4
#define HREF (MM / HALVES)    // 2500 refs per split
#define TILE4 1280            // 20 KB tile

// ---------------- device scratch (static: no allocation) ----------------
__device__ float4 g_noisy4[BB * NN];      // (x,y,z, x^2+y^2+z^2)
__device__ float4 g_clean4[BB * MM];
__device__ float4 g_forigin[BB * PP];
__device__ float  g_zpart[BB * PP * ZF];  // Ws1[3:]^T z + bs1 per (b,p)
__device__ float4 g_fpts[BB * PP * KS];   // gathered noisy neighbors
__device__ float  g_estim[BB * PP * KS * 3];
__device__ float4 g_hs[BB * PP * KS * HALVES];  // per-split top-4 scores
__device__ int4   g_hi[BB * PP * KS * HALVES];  // per-split top-4 ids
__device__ float  g_partial[64];

__device__ __forceinline__ float finf() { return __int_as_float(0x7f800000); }

// ---------------- K0: pack clouds + gather f_origin ----------------
__global__ void k0_pack(const float* __restrict__ noisy, const float* __restrict__ clean,
                        const int* __restrict__ sidx) {
    int i = blockIdx.x * blockDim.x + threadIdx.x;
    if (i < BB * NN) {
        float x = noisy[i * 3 + 0], y = noisy[i * 3 + 1], z = noisy[i * 3 + 2];
        g_noisy4[i] = make_float4(x, y, z, fmaf(x, x, fmaf(y, y, z * z)));
    }
    if (i < BB * MM) {
        float x = clean[i * 3 + 0], y = clean[i * 3 + 1], z = clean[i * 3 + 2];
        g_clean4[i] = make_float4(x, y, z, fmaf(x, x, fmaf(y, y, z * z)));
    }
    if (i < BB * PP) {
        int b = i >> 7, p = i & 127;
        const float* s = noisy + ((size_t)b * NN + sidx[p]) * 3;
        g_forigin[i] = make_float4(s[0], s[1], s[2], 0.f);
    }
}

// ---------------- K1: feat(sampled) -> zpart ----------------
__global__ void k1_feat(const float* __restrict__ Wf1, const float* __restrict__ bf1,
                        const float* __restrict__ Wf2, const float* __restrict__ bf2,
                        const float* __restrict__ Ws1, const float* __restrict__ bs1) {
    int bp = blockIdx.x;            // 0..511
    int tid = threadIdx.x;          // 128 threads
    __shared__ float h[64];
    __shared__ float z[128];

    float4 o = g_forigin[bp];

    if (tid < 64) {
        float a = bf1[tid];
        a = fmaf(o.x, Wf1[0 * 64 + tid], a);
        a = fmaf(o.y, Wf1[1 * 64 + tid], a);
        a = fmaf(o.z, Wf1[2 * 64 + tid], a);
        h[tid] = fmaxf(a, 0.f);
    }
    __syncthreads();

    {
        float a = bf2[tid];
#pragma unroll 16
        for (int i = 0; i < 64; ++i) a = fmaf(h[i], Wf2[i * 128 + tid], a);
        z[tid] = a;                 // feat: no relu on second layer
    }
    __syncthreads();

    {
        float a = bs1[tid];
#pragma unroll 16
        for (int i = 0; i < 128; ++i) a = fmaf(z[i], Ws1[(3 + i) * 128 + tid], a);
        g_zpart[bp * ZF + tid] = a;
    }
}

// ---------------- K2: KNN1 top-32 via 4-level radix select ----------------
__global__ __launch_bounds__(256) void k2_knn1() {
    int bp = blockIdx.x;            // one query per block
    int b = bp >> 7;
    int tid = threadIdx.x, lane = tid & 31;
    __shared__ unsigned keys[NN];   // 40 KB
    __shared__ unsigned hist[257];  // 256 bins + 1 dummy
    __shared__ unsigned s_prefix, s_want, s_cnt;

    float4 q = g_forigin[bp];
    float m2x = -2.0f * q.x, m2y = -2.0f * q.y, m2z = -2.0f * q.z;

    // level 0: fused key compute + histogram
    hist[tid] = 0u;
    if (tid == 0) hist[256] = 0u;
    __syncthreads();
    for (int r = tid; r < NN; r += 256) {
        float4 v = g_noisy4[b * NN + r];
        float s = fmaf(v.x, m2x, fmaf(v.y, m2y, fmaf(v.z, m2z, v.w))); // d2 - |q|^2
        unsigned u = __float_as_uint(s);
        u ^= ((unsigned)((int)u >> 31)) | 0x80000000u;  // monotone float->uint
        keys[r] = u;
        atomicAdd(&hist[u >> 24], 1u);
    }
    __syncthreads();

    unsigned prefix = 0u, want = 32u;
    for (int level = 0; level < 4; ++level) {
        const int shift = 24 - 8 * level;
        if (level > 0) {
            const unsigned mask = 0xFFFFFFFFu << (shift + 8);
            hist[tid] = 0u;
            if (tid == 0) hist[256] = 0u;
            __syncthreads();
            for (int r = tid; r < NN; r += 256) {
                unsigned k = keys[r];
                bool match = ((k ^ prefix) & mask) == 0u;
                unsigned bin = (k >> shift) & 0xFFu;
                atomicAdd(&hist[match ? bin : 256u], 1u);   // branchless (dummy bin)
            }
            __syncthreads();
        }
        if (tid < 32) {
            unsigned c[8], lsum = 0u;
#pragma unroll
            for (int j = 0; j < 8; ++j) { c[j] = hist[8 * lane + j]; lsum += c[j]; }
            unsigned incl = lsum;
#pragma unroll
            for (int off = 1; off < 32; off <<= 1) {
                unsigned t = __shfl_up_sync(0xFFFFFFFFu, incl, off);
                if (lane >= off) incl += t;
            }
            unsigned excl = incl - lsum;
            if (excl < want && want <= incl) {          // exactly one lane
                unsigned acc = excl;
#pragma unroll
                for (int j = 0; j < 8; ++j) {
                    if (want <= acc + c[j]) {
                        s_prefix = prefix | ((unsigned)(8 * lane + j) << shift);
                        s_want = want - acc;
                        break;
                    }
                    acc += c[j];
                }
            }
        }
        __syncthreads();
        prefix = s_prefix; want = s_want;
        __syncthreads();            // protect s_prefix before next level reuse
    }
    unsigned T = prefix;            // exact 32nd-smallest key

    if (tid == 0) s_cnt = 0u;
    __syncthreads();
    for (int r = tid; r < NN; r += 256) {
        if (keys[r] <= T) {
            unsigned pos = atomicAdd(&s_cnt, 1u);
            if (pos < 32u) g_fpts[bp * KS + pos] = g_noisy4[b * NN + r];
        }
    }
}

// ---------------- K3: score MLP — ONE WARP PER 4 ROWS ----------------
__global__ __launch_bounds__(256) void k3_mlp(const float* __restrict__ Ws1,
                                              const float* __restrict__ Ws2,
                                              const float* __restrict__ bs2,
                                              const float* __restrict__ Ws3,
                                              const float* __restrict__ bs3) {
    __shared__ float hsh[8][4][128];
    int w = threadIdx.x >> 5, lane = threadIdx.x & 31;
    int rbase = (blockIdx.x * 8 + w) * 4;   // rows rbase..rbase+3 share bp
    int bp = rbase >> 5;

    float4 o = g_forigin[bp];
    float X0[4], X1[4], X2[4];
#pragma unroll
    for (int j = 0; j < 4; ++j) {
        float4 f = g_fpts[rbase + j];       // warp-uniform address -> L1 broadcast
        X0[j] = f.x - o.x; X1[j] = f.y - o.y; X2[j] = f.z - o.z;
    }

    float4 zp = *(const float4*)(g_zpart + bp * ZF + lane * 4);
    float4 w0 = *(const float4*)(Ws1 + 0 * 128 + lane * 4);
    float4 w1 = *(const float4*)(Ws1 + 1 * 128 + lane * 4);
    float4 w2 = *(const float4*)(Ws1 + 2 * 128 + lane * 4);
#pragma unroll
    for (int j = 0; j < 4; ++j) {
        float4 h4;
        h4.x = fmaxf(fmaf(X2[j], w2.x, fmaf(X1[j], w1.x, fmaf(X0[j], w0.x, zp.x))), 0.f);
        h4.y = fmaxf(fmaf(X2[j], w2.y, fmaf(X1[j], w1.y, fmaf(X0[j], w0.y, zp.y))), 0.f);
        h4.z = fmaxf(fmaf(X2[j], w2.z, fmaf(X1[j], w1.z, fmaf(X0[j], w0.z, zp.z))), 0.f);
        h4.w = fmaxf(fmaf(X2[j], w2.w, fmaf(X1[j], w1.w, fmaf(X0[j], w0.w, zp.w))), 0.f);
        *(float4*)&hsh[w][j][lane * 4] = h4;
    }
    __syncwarp();

    float b20 = bs2[2 * lane], b21 = bs2[2 * lane + 1];
    float a0[4], a1[4];
#pragma unroll
    for (int j = 0; j < 4; ++j) { a0[j] = b20; a1[j] = b21; }
    const float2* __restrict__ W2 = (const float2*)(Ws2) + lane;  // (i, 2*lane)
#pragma unroll 8
    for (int i = 0; i < 128; i += 4) {
        float2 wv0 = W2[(i + 0) * 32];
        float2 wv1 = W2[(i + 1) * 32];
        float2 wv2 = W2[(i + 2) * 32];
        float2 wv3 = W2[(i + 3) * 32];
#pragma unroll
        for (int j = 0; j < 4; ++j) {
            float4 hv = *(const float4*)&hsh[w][j][i];   // broadcast LDS.128
            a0[j] = fmaf(hv.x, wv0.x, a0[j]); a1[j] = fmaf(hv.x, wv0.y, a1[j]);
            a0[j] = fmaf(hv.y, wv1.x, a0[j]); a1[j] = fmaf(hv.y, wv1.y, a1[j]);
            a0[j] = fmaf(hv.z, wv2.x, a0[j]); a1[j] = fmaf(hv.z, wv2.y, a1[j]);
            a0[j] = fmaf(hv.w, wv3.x, a0[j]); a1[j] = fmaf(hv.w, wv3.y, a1[j]);
        }
    }

    const float* __restrict__ w3 = Ws3 + 6 * lane;
    float w30 = w3[0], w31 = w3[1], w32 = w3[2];
    float w33 = w3[3], w34 = w3[4], w35 = w3[5];
    float ob0 = bs3[0], ob1 = bs3[1], ob2 = bs3[2];
#pragma unroll
    for (int j = 0; j < 4; ++j) {
        float h20 = fmaxf(a0[j], 0.f), h21 = fmaxf(a1[j], 0.f);
        float p0 = fmaf(h20, w30, h21 * w33);
        float p1 = fmaf(h20, w31, h21 * w34);
        float p2 = fmaf(h20, w32, h21 * w35);
#pragma unroll
        for (int off = 16; off > 0; off >>= 1) {
            p0 += __shfl_xor_sync(0xFFFFFFFFu, p0, off);
            p1 += __shfl_xor_sync(0xFFFFFFFFu, p1, off);
            p2 += __shfl_xor_sync(0xFFFFFFFFu, p2, off);
        }
        if (lane == 0) {
            g_estim[(rbase + j) * 3 + 0] = p0 + ob0;
            g_estim[(rbase + j) * 3 + 1] = p1 + ob1;
            g_estim[(rbase + j) * 3 + 2] = p2 + ob2;
        }
    }
}

// insertion into sorted 4-element top list
#define INS4(s, id, s0, s1, s2, s3, i0, i1, i2, i3)             \
    if ((s) < (s3)) {                                           \
        if ((s) < (s2)) {                                       \
            (s3) = (s2); (i3) = (i2);                           \
            if ((s) < (s1)) {                                   \
                (s2) = (s1); (i2) = (i1);                       \
                if ((s) < (s0)) { (s1) = (s0); (i1) = (i0); (s0) = (s); (i0) = (id); } \
                else { (s1) = (s); (i1) = (id); }               \
            } else { (s2) = (s); (i2) = (id); }                 \
        } else { (s3) = (s); (i3) = (id); }                     \
    }

// ---------------- K4: KNN2 top-4, 4-way ref-split, unroll-8 ----------------
__global__ __launch_bounds__(256) void k4_knn2() {
    int bid = blockIdx.x;                        // 2048 blocks
    int bp = bid >> 2, half = bid & 3;
    int b = bp >> 7;
    int tid = threadIdx.x, lane = tid & 31, w = tid >> 5;   // 8 warps
    __shared__ float4 buf[TILE4];                // 20 KB tile
    __shared__ float  cs[8][32][4];
    __shared__ int    ci[8][32][4];

    float4 f = g_fpts[bp * KS + lane];           // lane = query k
    float m2x = -2.0f * f.x, m2y = -2.0f * f.y, m2z = -2.0f * f.z;
    float s0 = finf(), s1 = finf(), s2 = finf(), s3 = finf();
    int   i0 = 0, i1 = 0, i2 = 0, i3 = 0;

    int base = half * HREF;
    for (int t0 = base; t0 < base + HREF; t0 += TILE4) {
        int n = min(TILE4, base + HREF - t0);
        __syncthreads();
        for (int j = tid; j < n; j += 256) buf[j] = g_clean4[b * MM + t0 + j];
        __syncthreads();
        int chunk = (n + 7) >> 3;
        int start = w * chunk;
        int end = min(start + chunk, n);
        int r = start;
        for (; r + 8 <= end; r += 8) {
            float4 v0 = buf[r + 0];
            float4 v1 = buf[r + 1];
            float4 v2 = buf[r + 2];
            float4 v3 = buf[r + 3];
            float sa = fmaf(v0.x, m2x, fmaf(v0.y, m2y, fmaf(v0.z, m2z, v0.w)));
            float sb = fmaf(v1.x, m2x, fmaf(v1.y, m2y, fmaf(v1.z, m2z, v1.w)));
            float sc = fmaf(v2.x, m2x, fmaf(v2.y, m2y, fmaf(v2.z, m2z, v2.w)));
            float sd = fmaf(v3.x, m2x, fmaf(v3.y, m2y, fmaf(v3.z, m2z, v3.w)));
            float4 v4 = buf[r + 4];
            float4 v5 = buf[r + 5];
            float4 v6 = buf[r + 6];
            float4 v7 = buf[r + 7];
            float se = fmaf(v4.x, m2x, fmaf(v4.y, m2y, fmaf(v4.z, m2z, v4.w)));
            float sf = fmaf(v5.x, m2x, fmaf(v5.y, m2y, fmaf(v5.z, m2z, v5.w)));
            float sg = fmaf(v6.x, m2x, fmaf(v6.y, m2y, fmaf(v6.z, m2z, v6.w)));
            float sh = fmaf(v7.x, m2x, fmaf(v7.y, m2y, fmaf(v7.z, m2z, v7.w)));
            float m = fminf(fminf(fminf(sa, sb), fminf(sc, sd)),
                            fminf(fminf(se, sf), fminf(sg, sh)));
            if (m < s3) {                        // rare
                INS4(sa, t0 + r + 0, s0, s1, s2, s3, i0, i1, i2, i3);
                INS4(sb, t0 + r + 1, s0, s1, s2, s3, i0, i1, i2, i3);
                INS4(sc, t0 + r + 2, s0, s1, s2, s3, i0, i1, i2, i3);
                INS4(sd, t0 + r + 3, s0, s1, s2, s3, i0, i1, i2, i3);
                INS4(se, t0 + r + 4, s0, s1, s2, s3, i0, i1, i2, i3);
                INS4(sf, t0 + r + 5, s0, s1, s2, s3, i0, i1, i2, i3);
                INS4(sg, t0 + r + 6, s0, s1, s2, s3, i0, i1, i2, i3);
                INS4(sh, t0 + r + 7, s0, s1, s2, s3, i0, i1, i2, i3);
            }
        }
        for (; r < end; ++r) {
            float4 v = buf[r];
            float s = fmaf(v.x, m2x, fmaf(v.y, m2y, fmaf(v.z, m2z, v.w)));
            int id = t0 + r;
            INS4(s, id, s0, s1, s2, s3, i0, i1, i2, i3);
        }
    }
    cs[w][lane][0] = s0; cs[w][lane][1] = s1; cs[w][lane][2] = s2; cs[w][lane][3] = s3;
    ci[w][lane][0] = i0; ci[w][lane][1] = i1; ci[w][lane][2] = i2; ci[w][lane][3] = i3;
    __syncthreads();

    if (w == 0) {
        float b0 = finf(), b1 = finf(), b2 = finf(), b3 = finf();
        int   j0 = 0, j1 = 0, j2 = 0, j3 = 0;
#pragma unroll
        for (int ww = 0; ww < 8; ++ww)
#pragma unroll
            for (int jj = 0; jj < 4; ++jj) {
                float s = cs[ww][lane][jj];
                int id = ci[ww][lane][jj];
                INS4(s, id, b0, b1, b2, b3, j0, j1, j2, j3);
            }
        int row = bp * KS + lane;
        g_hs[row * HALVES + half] = make_float4(b0, b1, b2, b3);
        g_hi[row * HALVES + half] = make_int4(j0, j1, j2, j3);
    }
}

// ---------------- K5a: merge splits + ground score + loss partials ----------
__global__ __launch_bounds__(256) void k5a_merge() {
    __shared__ float red[256];
    int tid = threadIdx.x;
    int row = blockIdx.x * 256 + tid;            // 64 blocks -> 16384 rows
    int b = row >> 12;

    float s0 = finf(), s1 = finf(), s2 = finf(), s3 = finf();
    int   j0 = 0, j1 = 0, j2 = 0, j3 = 0;
#pragma unroll
    for (int h = 0; h < HALVES; ++h) {           // index order preserves tie rule
        float4 sc = g_hs[row * HALVES + h];
        int4   id = g_hi[row * HALVES + h];
        INS4(sc.x, id.x, s0, s1, s2, s3, j0, j1, j2, j3);
        INS4(sc.y, id.y, s0, s1, s2, s3, j0, j1, j2, j3);
        INS4(sc.z, id.z, s0, s1, s2, s3, j0, j1, j2, j3);
        INS4(sc.w, id.w, s0, s1, s2, s3, j0, j1, j2, j3);
    }
    float4 c0 = g_clean4[b * MM + j0];
    float4 c1 = g_clean4[b * MM + j1];
    float4 c2 = g_clean4[b * MM + j2];
    float4 c3 = g_clean4[b * MM + j3];
    float4 f = g_fpts[row];
    float gx = (c0.x + c1.x + c2.x + c3.x) * 0.25f - f.x;
    float gy = (c0.y + c1.y + c2.y + c3.y) * 0.25f - f.y;
    float gz = (c0.z + c1.z + c2.z + c3.z) * 0.25f - f.z;
    const float* e = g_estim + row * 3;
    float d0 = e[0] - gx, d1 = e[1] - gy, d2 = e[2] - gz;
    red[tid] = fmaf(d0, d0, fmaf(d1, d1, d2 * d2));
    __syncthreads();
#pragma unroll
    for (int s = 128; s > 0; s >>= 1) {
        if (tid < s) red[tid] += red[tid + s];
        __syncthreads();
    }
    if (tid == 0) g_partial[blockIdx.x] = red[0];
}

// ---------------- K5b: deterministic final reduce ----------------
__global__ void k5b_reduce(float* __restrict__ out) {
    __shared__ float sm[64];
    int tid = threadIdx.x;
    sm[tid] = g_partial[tid];
    __syncthreads();
#pragma unroll
    for (int s = 32; s > 0; s >>= 1) {
        if (tid < s) sm[tid] += sm[tid + s];
        __syncthreads();
    }
    // loss = 0.5 * mean_{B*P*K}( sum_d (.)^2 / SIGMA ) = total * 0.5*100/16384
    if (tid == 0) out[0] = sm[0] * (50.0f / 16384.0f);
}

extern "C" void kernel_launch(void* const* d_in, const int* in_sizes, int n_in,
                              void* d_out, int out_size) {
    const float* noisy = (const float*)d_in[0];
    const float* clean = (const float*)d_in[1];
    const int*   sidx  = (const int*)d_in[2];
    const float* Wf1 = (const float*)d_in[3];
    const float* bf1 = (const float*)d_in[4];
    const float* Wf2 = (const float*)d_in[5];
    const float* bf2 = (const float*)d_in[6];
    const float* Ws1 = (const float*)d_in[7];
    const float* bs1 = (const float*)d_in[8];
    const float* Ws2 = (const float*)d_in[9];
    const float* bs2 = (const float*)d_in[10];
    const float* Ws3 = (const float*)d_in[11];
    const float* bs3 = (const float*)d_in[12];
    float* out = (float*)d_out;

    k0_pack<<<(BB * NN + 255) / 256, 256>>>(noisy, clean, sidx);
    k1_feat<<<BB * PP, 128>>>(Wf1, bf1, Wf2, bf2, Ws1, bs1);
    k2_knn1<<<BB * PP, 256>>>();
    k3_mlp<<<BB * PP * KS / 32, 256>>>(Ws1, Ws2, bs2, Ws3, bs3);
    k4_knn2<<<BB * PP * HALVES, 256>>>();
    k5a_merge<<<64, 256>>>();
    k5b_reduce<<<1, 64>>>(out);
}

// round 11
// speedup vs baseline: 1.0710x; 1.0710x over previous
#include <cuda_runtime.h>
#include <cuda_bf16.h>

#define BB 4
#define NN 10000
#define MM 10000
#define PP 128
#define KS 32
#define ZF 128

// ---------------- device scratch (static: no allocation) ----------------
__device__ float4 g_noisy4[BB * NN];      // (x,y,z, x^2+y^2+z^2)
__device__ float4 g_clean4[BB * MM];
__device__ float4 g_forigin[BB * PP];
__device__ float  g_zpart[BB * PP * ZF];  // Ws1[3:]^T z + bs1 per (b,p)
__device__ float4 g_fpts[BB * PP * KS];   // gathered noisy neighbors
__device__ float  g_estim[BB * PP * KS * 3];
__device__ float  g_partial[BB * PP];

__device__ __forceinline__ float finf() { return __int_as_float(0x7f800000); }

// ---------------- K0: pack clouds + gather f_origin ----------------
__global__ void k0_pack(const float* __restrict__ noisy, const float* __restrict__ clean,
                        const int* __restrict__ sidx) {
    int i = blockIdx.x * blockDim.x + threadIdx.x;
    if (i < BB * NN) {
        float x = noisy[i * 3 + 0], y = noisy[i * 3 + 1], z = noisy[i * 3 + 2];
        g_noisy4[i] = make_float4(x, y, z, fmaf(x, x, fmaf(y, y, z * z)));
    }
    if (i < BB * MM) {
        float x = clean[i * 3 + 0], y = clean[i * 3 + 1], z = clean[i * 3 + 2];
        g_clean4[i] = make_float4(x, y, z, fmaf(x, x, fmaf(y, y, z * z)));
    }
    if (i < BB * PP) {
        int b = i >> 7, p = i & 127;
        const float* s = noisy + ((size_t)b * NN + sidx[p]) * 3;
        g_forigin[i] = make_float4(s[0], s[1], s[2], 0.f);
    }
}

// ---------------- K1: feat(sampled) -> zpart ----------------
__global__ void k1_feat(const float* __restrict__ Wf1, const float* __restrict__ bf1,
                        const float* __restrict__ Wf2, const float* __restrict__ bf2,
                        const float* __restrict__ Ws1, const float* __restrict__ bs1) {
    int bp = blockIdx.x;            // 0..511
    int tid = threadIdx.x;          // 128 threads
    __shared__ float h[64];
    __shared__ float z[128];

    float4 o = g_forigin[bp];

    if (tid < 64) {
        float a = bf1[tid];
        a = fmaf(o.x, Wf1[0 * 64 + tid], a);
        a = fmaf(o.y, Wf1[1 * 64 + tid], a);
        a = fmaf(o.z, Wf1[2 * 64 + tid], a);
        h[tid] = fmaxf(a, 0.f);
    }
    __syncthreads();

    {
        float a = bf2[tid];
#pragma unroll 16
        for (int i = 0; i < 64; ++i) a = fmaf(h[i], Wf2[i * 128 + tid], a);
        z[tid] = a;                 // feat: no relu on second layer
    }
    __syncthreads();

    {
        float a = bs1[tid];
#pragma unroll 16
        for (int i = 0; i < 128; ++i) a = fmaf(z[i], Ws1[(3 + i) * 128 + tid], a);
        g_zpart[bp * ZF + tid] = a;
    }
}

// ---------------- K2: KNN1 top-32, radix select (fused L0, predicated atomics) --
__global__ __launch_bounds__(256) void k2_knn1() {
    int bp = blockIdx.x;            // one query per block
    int b = bp >> 7;
    int tid = threadIdx.x, lane = tid & 31;
    __shared__ unsigned keys[NN];   // 40 KB
    __shared__ unsigned hist[256];
    __shared__ unsigned s_prefix, s_want, s_cnt;

    float4 q = g_forigin[bp];
    float m2x = -2.0f * q.x, m2y = -2.0f * q.y, m2z = -2.0f * q.z;

    // level 0: fused key compute + histogram
    hist[tid] = 0u;
    __syncthreads();
    for (int r = tid; r < NN; r += 256) {
        float4 v = g_noisy4[b * NN + r];
        float s = fmaf(v.x, m2x, fmaf(v.y, m2y, fmaf(v.z, m2z, v.w))); // d2 - |q|^2
        unsigned u = __float_as_uint(s);
        u ^= ((unsigned)((int)u >> 31)) | 0x80000000u;  // monotone float->uint
        keys[r] = u;
        atomicAdd(&hist[u >> 24], 1u);
    }
    __syncthreads();

    unsigned prefix = 0u, want = 32u;
    for (int level = 0; level < 4; ++level) {
        const int shift = 24 - 8 * level;
        if (level > 0) {
            const unsigned mask = 0xFFFFFFFFu << (shift + 8);
            hist[tid] = 0u;
            __syncthreads();
            for (int r = tid; r < NN; r += 256) {
                unsigned k = keys[r];
                if (((k ^ prefix) & mask) == 0u)         // predicated: few match
                    atomicAdd(&hist[(k >> shift) & 0xFFu], 1u);
            }
            __syncthreads();
        }
        if (tid < 32) {
            unsigned c[8], lsum = 0u;
#pragma unroll
            for (int j = 0; j < 8; ++j) { c[j] = hist[8 * lane + j]; lsum += c[j]; }
            unsigned incl = lsum;
#pragma unroll
            for (int off = 1; off < 32; off <<= 1) {
                unsigned t = __shfl_up_sync(0xFFFFFFFFu, incl, off);
                if (lane >= off) incl += t;
            }
            unsigned excl = incl - lsum;
            if (excl < want && want <= incl) {          // exactly one lane
                unsigned acc = excl;
#pragma unroll
                for (int j = 0; j < 8; ++j) {
                    if (want <= acc + c[j]) {
                        s_prefix = prefix | ((unsigned)(8 * lane + j) << shift);
                        s_want = want - acc;
                        break;
                    }
                    acc += c[j];
                }
            }
        }
        __syncthreads();
        prefix = s_prefix; want = s_want;
        __syncthreads();            // protect s_prefix before next level reuse
    }
    unsigned T = prefix;            // exact 32nd-smallest key

    if (tid == 0) s_cnt = 0u;
    __syncthreads();
    for (int r = tid; r < NN; r += 256) {
        if (keys[r] <= T) {
            unsigned pos = atomicAdd(&s_cnt, 1u);
            if (pos < 32u) g_fpts[bp * KS + pos] = g_noisy4[b * NN + r];
        }
    }
}

// ---------------- K3: score MLP — ONE WARP PER 4 ROWS ----------------
__global__ __launch_bounds__(256) void k3_mlp(const float* __restrict__ Ws1,
                                              const float* __restrict__ Ws2,
                                              const float* __restrict__ bs2,
                                              const float* __restrict__ Ws3,
                                              const float* __restrict__ bs3) {
    __shared__ float hsh[8][4][128];
    int w = threadIdx.x >> 5, lane = threadIdx.x & 31;
    int rbase = (blockIdx.x * 8 + w) * 4;   // rows rbase..rbase+3 share bp
    int bp = rbase >> 5;

    float4 o = g_forigin[bp];
    float X0[4], X1[4], X2[4];
#pragma unroll
    for (int j = 0; j < 4; ++j) {
        float4 f = g_fpts[rbase + j];       // warp-uniform address -> L1 broadcast
        X0[j] = f.x - o.x; X1[j] = f.y - o.y; X2[j] = f.z - o.z;
    }

    float4 zp = *(const float4*)(g_zpart + bp * ZF + lane * 4);
    float4 w0 = *(const float4*)(Ws1 + 0 * 128 + lane * 4);
    float4 w1 = *(const float4*)(Ws1 + 1 * 128 + lane * 4);
    float4 w2 = *(const float4*)(Ws1 + 2 * 128 + lane * 4);
#pragma unroll
    for (int j = 0; j < 4; ++j) {
        float4 h4;
        h4.x = fmaxf(fmaf(X2[j], w2.x, fmaf(X1[j], w1.x, fmaf(X0[j], w0.x, zp.x))), 0.f);
        h4.y = fmaxf(fmaf(X2[j], w2.y, fmaf(X1[j], w1.y, fmaf(X0[j], w0.y, zp.y))), 0.f);
        h4.z = fmaxf(fmaf(X2[j], w2.z, fmaf(X1[j], w1.z, fmaf(X0[j], w0.z, zp.z))), 0.f);
        h4.w = fmaxf(fmaf(X2[j], w2.w, fmaf(X1[j], w1.w, fmaf(X0[j], w0.w, zp.w))), 0.f);
        *(float4*)&hsh[w][j][lane * 4] = h4;
    }
    __syncwarp();

    float b20 = bs2[2 * lane], b21 = bs2[2 * lane + 1];
    float a0[4], a1[4];
#pragma unroll
    for (int j = 0; j < 4; ++j) { a0[j] = b20; a1[j] = b21; }
    const float2* __restrict__ W2 = (const float2*)(Ws2) + lane;  // (i, 2*lane)
#pragma unroll 8
    for (int i = 0; i < 128; i += 4) {
        float2 wv0 = W2[(i + 0) * 32];
        float2 wv1 = W2[(i + 1) * 32];
        float2 wv2 = W2[(i + 2) * 32];
        float2 wv3 = W2[(i + 3) * 32];
#pragma unroll
        for (int j = 0; j < 4; ++j) {
            float4 hv = *(const float4*)&hsh[w][j][i];   // broadcast LDS.128
            a0[j] = fmaf(hv.x, wv0.x, a0[j]); a1[j] = fmaf(hv.x, wv0.y, a1[j]);
            a0[j] = fmaf(hv.y, wv1.x, a0[j]); a1[j] = fmaf(hv.y, wv1.y, a1[j]);
            a0[j] = fmaf(hv.z, wv2.x, a0[j]); a1[j] = fmaf(hv.z, wv2.y, a1[j]);
            a0[j] = fmaf(hv.w, wv3.x, a0[j]); a1[j] = fmaf(hv.w, wv3.y, a1[j]);
        }
    }

    const float* __restrict__ w3 = Ws3 + 6 * lane;
    float w30 = w3[0], w31 = w3[1], w32 = w3[2];
    float w33 = w3[3], w34 = w3[4], w35 = w3[5];
    float ob0 = bs3[0], ob1 = bs3[1], ob2 = bs3[2];
#pragma unroll
    for (int j = 0; j < 4; ++j) {
        float h20 = fmaxf(a0[j], 0.f), h21 = fmaxf(a1[j], 0.f);
        float p0 = fmaf(h20, w30, h21 * w33);
        float p1 = fmaf(h20, w31, h21 * w34);
        float p2 = fmaf(h20, w32, h21 * w35);
#pragma unroll
        for (int off = 16; off > 0; off >>= 1) {
            p0 += __shfl_xor_sync(0xFFFFFFFFu, p0, off);
            p1 += __shfl_xor_sync(0xFFFFFFFFu, p1, off);
            p2 += __shfl_xor_sync(0xFFFFFFFFu, p2, off);
        }
        if (lane == 0) {
            g_estim[(rbase + j) * 3 + 0] = p0 + ob0;
            g_estim[(rbase + j) * 3 + 1] = p1 + ob1;
            g_estim[(rbase + j) * 3 + 2] = p2 + ob2;
        }
    }
}

// insertion into sorted 4-element top list
#define INS4(s, id, s0, s1, s2, s3, i0, i1, i2, i3)             \
    if ((s) < (s3)) {                                           \
        if ((s) < (s2)) {                                       \
            (s3) = (s2); (i3) = (i2);                           \
            if ((s) < (s1)) {                                   \
                (s2) = (s1); (i2) = (i1);                       \
                if ((s) < (s0)) { (s1) = (s0); (i1) = (i0); (s0) = (s); (i0) = (id); } \
                else { (s1) = (s); (i1) = (id); }               \
            } else { (s2) = (s); (i2) = (id); }                 \
        } else { (s3) = (s); (i3) = (id); }                     \
    }

// ---------------- K4: KNN2 top-4, grouped compare (R5 winner) ----------------
__global__ __launch_bounds__(256) void k4_knn2() {
    int bp = blockIdx.x;
    int b = bp >> 7;
    int tid = threadIdx.x, lane = tid & 31, w = tid >> 5;   // 8 warps
    __shared__ float4 buf[2048];                 // 32 KB tile
    __shared__ float  cs[8][32][4];
    __shared__ int    ci[8][32][4];

    float4 f = g_fpts[bp * KS + lane];           // lane = query k
    float m2x = -2.0f * f.x, m2y = -2.0f * f.y, m2z = -2.0f * f.z;
    float s0 = finf(), s1 = finf(), s2 = finf(), s3 = finf();
    int   i0 = 0, i1 = 0, i2 = 0, i3 = 0;

    for (int t0 = 0; t0 < MM; t0 += 2048) {
        int n = min(2048, MM - t0);
        __syncthreads();
        for (int j = tid; j < n; j += 256) buf[j] = g_clean4[b * MM + t0 + j];
        __syncthreads();
        int chunk = (n + 7) >> 3;
        int start = w * chunk;
        int end = min(start + chunk, n);
        int r = start;
#pragma unroll 2
        for (; r + 4 <= end; r += 4) {
            float4 v0 = buf[r + 0];
            float4 v1 = buf[r + 1];
            float4 v2 = buf[r + 2];
            float4 v3 = buf[r + 3];
            float sa = fmaf(v0.x, m2x, fmaf(v0.y, m2y, fmaf(v0.z, m2z, v0.w)));
            float sb = fmaf(v1.x, m2x, fmaf(v1.y, m2y, fmaf(v1.z, m2z, v1.w)));
            float sc = fmaf(v2.x, m2x, fmaf(v2.y, m2y, fmaf(v2.z, m2z, v2.w)));
            float sd = fmaf(v3.x, m2x, fmaf(v3.y, m2y, fmaf(v3.z, m2z, v3.w)));
            float m = fminf(fminf(sa, sb), fminf(sc, sd));
            if (m < s3) {                        // rare: ~30x per 10000
                INS4(sa, t0 + r + 0, s0, s1, s2, s3, i0, i1, i2, i3);
                INS4(sb, t0 + r + 1, s0, s1, s2, s3, i0, i1, i2, i3);
                INS4(sc, t0 + r + 2, s0, s1, s2, s3, i0, i1, i2, i3);
                INS4(sd, t0 + r + 3, s0, s1, s2, s3, i0, i1, i2, i3);
            }
        }
        for (; r < end; ++r) {
            float4 v = buf[r];
            float s = fmaf(v.x, m2x, fmaf(v.y, m2y, fmaf(v.z, m2z, v.w)));
            int id = t0 + r;
            INS4(s, id, s0, s1, s2, s3, i0, i1, i2, i3);
        }
    }
    cs[w][lane][0] = s0; cs[w][lane][1] = s1; cs[w][lane][2] = s2; cs[w][lane][3] = s3;
    ci[w][lane][0] = i0; ci[w][lane][1] = i1; ci[w][lane][2] = i2; ci[w][lane][3] = i3;
    __syncthreads();

    if (w == 0) {
        float b0 = finf(), b1 = finf(), b2 = finf(), b3 = finf();
        int   j0 = 0, j1 = 0, j2 = 0, j3 = 0;
#pragma unroll
        for (int ww = 0; ww < 8; ++ww)
#pragma unroll
            for (int jj = 0; jj < 4; ++jj) {
                float s = cs[ww][lane][jj];
                int id = ci[ww][lane][jj];
                INS4(s, id, b0, b1, b2, b3, j0, j1, j2, j3);
            }
        float4 c0 = g_clean4[b * MM + j0];
        float4 c1 = g_clean4[b * MM + j1];
        float4 c2 = g_clean4[b * MM + j2];
        float4 c3 = g_clean4[b * MM + j3];
        float gx = (c0.x + c1.x + c2.x + c3.x) * 0.25f - f.x;
        float gy = (c0.y + c1.y + c2.y + c3.y) * 0.25f - f.y;
        float gz = (c0.z + c1.z + c2.z + c3.z) * 0.25f - f.z;
        const float* e = g_estim + (bp * KS + lane) * 3;
        float d0 = e[0] - gx, d1 = e[1] - gy, d2v = e[2] - gz;
        float err = fmaf(d0, d0, fmaf(d1, d1, d2v * d2v));
#pragma unroll
        for (int off = 16; off > 0; off >>= 1)
            err += __shfl_xor_sync(0xFFFFFFFFu, err, off);
        if (lane == 0) g_partial[bp] = err;
    }
}

// ---------------- K5: deterministic final reduce ----------------
__global__ void k5_reduce(float* __restrict__ out) {
    __shared__ float sm[512];
    int tid = threadIdx.x;
    sm[tid] = g_partial[tid];
    __syncthreads();
#pragma unroll
    for (int s = 256; s > 0; s >>= 1) {
        if (tid < s) sm[tid] += sm[tid + s];
        __syncthreads();
    }
    // loss = 0.5 * mean_{B*P*K}( sum_d (.)^2 / SIGMA ) = total * 0.5*100/16384
    if (tid == 0) out[0] = sm[0] * (50.0f / 16384.0f);
}

extern "C" void kernel_launch(void* const* d_in, const int* in_sizes, int n_in,
                              void* d_out, int out_size) {
    const float* noisy = (const float*)d_in[0];
    const float* clean = (const float*)d_in[1];
    const int*   sidx  = (const int*)d_in[2];
    const float* Wf1 = (const float*)d_in[3];
    const float* bf1 = (const float*)d_in[4];
    const float* Wf2 = (const float*)d_in[5];
    const float* bf2 = (const float*)d_in[6];
    const float* Ws1 = (const float*)d_in[7];
    const float* bs1 = (const float*)d_in[8];
    const float* Ws2 = (const float*)d_in[9];
    const float* bs2 = (const float*)d_in[10];
    const float* Ws3 = (const float*)d_in[11];
    const float* bs3 = (const float*)d_in[12];
    float* out = (float*)d_out;

    k0_pack<<<(BB * NN + 255) / 256, 256>>>(noisy, clean, sidx);
    k1_feat<<<BB * PP, 128>>>(Wf1, bf1, Wf2, bf2, Ws1, bs1);
    k2_knn1<<<BB * PP, 256>>>();
    k3_mlp<<<BB * PP * KS / 32, 256>>>(Ws1, Ws2, bs2, Ws3, bs3);
    k4_knn2<<<BB * PP, 256>>>();
    k5_reduce<<<1, 512>>>(out);
}

// round 12
// speedup vs baseline: 1.2233x; 1.1422x over previous
#include <cuda_runtime.h>
#include <cuda_bf16.h>

#define BB 4
#define NN 10000
#define MM 10000
#define PP 128
#define KS 32
#define ZF 128

// ---------------- device scratch (static: no allocation) ----------------
__device__ float4 g_noisy4[BB * NN];      // (x,y,z, x^2+y^2+z^2)
__device__ float4 g_clean4[BB * MM];
__device__ float4 g_forigin[BB * PP];
__device__ float  g_zpart[BB * PP * ZF];  // Ws1[3:]^T z + bs1 per (b,p)
__device__ float4 g_fpts[BB * PP * KS];   // gathered noisy neighbors
__device__ float  g_estim[BB * PP * KS * 3];
__device__ float  g_partial[BB * PP];

__device__ __forceinline__ float finf() { return __int_as_float(0x7f800000); }

// ---------------- K0: pack clouds + gather f_origin ----------------
__global__ void k0_pack(const float* __restrict__ noisy, const float* __restrict__ clean,
                        const int* __restrict__ sidx) {
    int i = blockIdx.x * blockDim.x + threadIdx.x;
    if (i < BB * NN) {
        float x = noisy[i * 3 + 0], y = noisy[i * 3 + 1], z = noisy[i * 3 + 2];
        g_noisy4[i] = make_float4(x, y, z, fmaf(x, x, fmaf(y, y, z * z)));
    }
    if (i < BB * MM) {
        float x = clean[i * 3 + 0], y = clean[i * 3 + 1], z = clean[i * 3 + 2];
        g_clean4[i] = make_float4(x, y, z, fmaf(x, x, fmaf(y, y, z * z)));
    }
    if (i < BB * PP) {
        int b = i >> 7, p = i & 127;
        const float* s = noisy + ((size_t)b * NN + sidx[p]) * 3;
        g_forigin[i] = make_float4(s[0], s[1], s[2], 0.f);
    }
}

// ---------------- K1: feat(sampled) -> zpart ----------------
__global__ void k1_feat(const float* __restrict__ Wf1, const float* __restrict__ bf1,
                        const float* __restrict__ Wf2, const float* __restrict__ bf2,
                        const float* __restrict__ Ws1, const float* __restrict__ bs1) {
    int bp = blockIdx.x;            // 0..511
    int tid = threadIdx.x;          // 128 threads
    __shared__ float h[64];
    __shared__ float z[128];

    float4 o = g_forigin[bp];

    if (tid < 64) {
        float a = bf1[tid];
        a = fmaf(o.x, Wf1[0 * 64 + tid], a);
        a = fmaf(o.y, Wf1[1 * 64 + tid], a);
        a = fmaf(o.z, Wf1[2 * 64 + tid], a);
        h[tid] = fmaxf(a, 0.f);
    }
    __syncthreads();

    {
        float a = bf2[tid];
#pragma unroll 16
        for (int i = 0; i < 64; ++i) a = fmaf(h[i], Wf2[i * 128 + tid], a);
        z[tid] = a;                 // feat: no relu on second layer
    }
    __syncthreads();

    {
        float a = bs1[tid];
#pragma unroll 16
        for (int i = 0; i < 128; ++i) a = fmaf(z[i], Ws1[(3 + i) * 128 + tid], a);
        g_zpart[bp * ZF + tid] = a;
    }
}

// ---------------- K2: KNN1 top-32, radix select (fused L0, predicated atomics) --
__global__ __launch_bounds__(256) void k2_knn1() {
    int bp = blockIdx.x;            // one query per block
    int b = bp >> 7;
    int tid = threadIdx.x, lane = tid & 31;
    __shared__ unsigned keys[NN];   // 40 KB
    __shared__ unsigned hist[256];
    __shared__ unsigned s_prefix, s_want, s_cnt;

    float4 q = g_forigin[bp];
    float m2x = -2.0f * q.x, m2y = -2.0f * q.y, m2z = -2.0f * q.z;

    // level 0: fused key compute + histogram
    hist[tid] = 0u;
    __syncthreads();
    for (int r = tid; r < NN; r += 256) {
        float4 v = g_noisy4[b * NN + r];
        float s = fmaf(v.x, m2x, fmaf(v.y, m2y, fmaf(v.z, m2z, v.w))); // d2 - |q|^2
        unsigned u = __float_as_uint(s);
        u ^= ((unsigned)((int)u >> 31)) | 0x80000000u;  // monotone float->uint
        keys[r] = u;
        atomicAdd(&hist[u >> 24], 1u);
    }
    __syncthreads();

    unsigned prefix = 0u, want = 32u;
    for (int level = 0; level < 4; ++level) {
        const int shift = 24 - 8 * level;
        if (level > 0) {
            const unsigned mask = 0xFFFFFFFFu << (shift + 8);
            hist[tid] = 0u;
            __syncthreads();
            for (int r = tid; r < NN; r += 256) {
                unsigned k = keys[r];
                if (((k ^ prefix) & mask) == 0u)         // predicated: few match
                    atomicAdd(&hist[(k >> shift) & 0xFFu], 1u);
            }
            __syncthreads();
        }
        if (tid < 32) {
            unsigned c[8], lsum = 0u;
#pragma unroll
            for (int j = 0; j < 8; ++j) { c[j] = hist[8 * lane + j]; lsum += c[j]; }
            unsigned incl = lsum;
#pragma unroll
            for (int off = 1; off < 32; off <<= 1) {
                unsigned t = __shfl_up_sync(0xFFFFFFFFu, incl, off);
                if (lane >= off) incl += t;
            }
            unsigned excl = incl - lsum;
            if (excl < want && want <= incl) {          // exactly one lane
                unsigned acc = excl;
#pragma unroll
                for (int j = 0; j < 8; ++j) {
                    if (want <= acc + c[j]) {
                        s_prefix = prefix | ((unsigned)(8 * lane + j) << shift);
                        s_want = want - acc;
                        break;
                    }
                    acc += c[j];
                }
            }
        }
        __syncthreads();
        prefix = s_prefix; want = s_want;
        __syncthreads();            // protect s_prefix before next level reuse
    }
    unsigned T = prefix;            // exact 32nd-smallest key

    if (tid == 0) s_cnt = 0u;
    __syncthreads();
    for (int r = tid; r < NN; r += 256) {
        if (keys[r] <= T) {
            unsigned pos = atomicAdd(&s_cnt, 1u);
            if (pos < 32u) g_fpts[bp * KS + pos] = g_noisy4[b * NN + r];
        }
    }
}

// ---------------- K3: score MLP — ONE WARP PER 4 ROWS ----------------
__global__ __launch_bounds__(256) void k3_mlp(const float* __restrict__ Ws1,
                                              const float* __restrict__ Ws2,
                                              const float* __restrict__ bs2,
                                              const float* __restrict__ Ws3,
                                              const float* __restrict__ bs3) {
    __shared__ float hsh[8][4][128];
    int w = threadIdx.x >> 5, lane = threadIdx.x & 31;
    int rbase = (blockIdx.x * 8 + w) * 4;   // rows rbase..rbase+3 share bp
    int bp = rbase >> 5;

    float4 o = g_forigin[bp];
    float X0[4], X1[4], X2[4];
#pragma unroll
    for (int j = 0; j < 4; ++j) {
        float4 f = g_fpts[rbase + j];       // warp-uniform address -> L1 broadcast
        X0[j] = f.x - o.x; X1[j] = f.y - o.y; X2[j] = f.z - o.z;
    }

    float4 zp = *(const float4*)(g_zpart + bp * ZF + lane * 4);
    float4 w0 = *(const float4*)(Ws1 + 0 * 128 + lane * 4);
    float4 w1 = *(const float4*)(Ws1 + 1 * 128 + lane * 4);
    float4 w2 = *(const float4*)(Ws1 + 2 * 128 + lane * 4);
#pragma unroll
    for (int j = 0; j < 4; ++j) {
        float4 h4;
        h4.x = fmaxf(fmaf(X2[j], w2.x, fmaf(X1[j], w1.x, fmaf(X0[j], w0.x, zp.x))), 0.f);
        h4.y = fmaxf(fmaf(X2[j], w2.y, fmaf(X1[j], w1.y, fmaf(X0[j], w0.y, zp.y))), 0.f);
        h4.z = fmaxf(fmaf(X2[j], w2.z, fmaf(X1[j], w1.z, fmaf(X0[j], w0.z, zp.z))), 0.f);
        h4.w = fmaxf(fmaf(X2[j], w2.w, fmaf(X1[j], w1.w, fmaf(X0[j], w0.w, zp.w))), 0.f);
        *(float4*)&hsh[w][j][lane * 4] = h4;
    }
    __syncwarp();

    float b20 = bs2[2 * lane], b21 = bs2[2 * lane + 1];
    float a0[4], a1[4];
#pragma unroll
    for (int j = 0; j < 4; ++j) { a0[j] = b20; a1[j] = b21; }
    const float2* __restrict__ W2 = (const float2*)(Ws2) + lane;  // (i, 2*lane)
#pragma unroll 8
    for (int i = 0; i < 128; i += 4) {
        float2 wv0 = W2[(i + 0) * 32];
        float2 wv1 = W2[(i + 1) * 32];
        float2 wv2 = W2[(i + 2) * 32];
        float2 wv3 = W2[(i + 3) * 32];
#pragma unroll
        for (int j = 0; j < 4; ++j) {
            float4 hv = *(const float4*)&hsh[w][j][i];   // broadcast LDS.128
            a0[j] = fmaf(hv.x, wv0.x, a0[j]); a1[j] = fmaf(hv.x, wv0.y, a1[j]);
            a0[j] = fmaf(hv.y, wv1.x, a0[j]); a1[j] = fmaf(hv.y, wv1.y, a1[j]);
            a0[j] = fmaf(hv.z, wv2.x, a0[j]); a1[j] = fmaf(hv.z, wv2.y, a1[j]);
            a0[j] = fmaf(hv.w, wv3.x, a0[j]); a1[j] = fmaf(hv.w, wv3.y, a1[j]);
        }
    }

    const float* __restrict__ w3 = Ws3 + 6 * lane;
    float w30 = w3[0], w31 = w3[1], w32 = w3[2];
    float w33 = w3[3], w34 = w3[4], w35 = w3[5];
    float ob0 = bs3[0], ob1 = bs3[1], ob2 = bs3[2];
#pragma unroll
    for (int j = 0; j < 4; ++j) {
        float h20 = fmaxf(a0[j], 0.f), h21 = fmaxf(a1[j], 0.f);
        float p0 = fmaf(h20, w30, h21 * w33);
        float p1 = fmaf(h20, w31, h21 * w34);
        float p2 = fmaf(h20, w32, h21 * w35);
#pragma unroll
        for (int off = 16; off > 0; off >>= 1) {
            p0 += __shfl_xor_sync(0xFFFFFFFFu, p0, off);
            p1 += __shfl_xor_sync(0xFFFFFFFFu, p1, off);
            p2 += __shfl_xor_sync(0xFFFFFFFFu, p2, off);
        }
        if (lane == 0) {
            g_estim[(rbase + j) * 3 + 0] = p0 + ob0;
            g_estim[(rbase + j) * 3 + 1] = p1 + ob1;
            g_estim[(rbase + j) * 3 + 2] = p2 + ob2;
        }
    }
}

// insertion into sorted 4-element top list
#define INS4(s, id, s0, s1, s2, s3, i0, i1, i2, i3)             \
    if ((s) < (s3)) {                                           \
        if ((s) < (s2)) {                                       \
            (s3) = (s2); (i3) = (i2);                           \
            if ((s) < (s1)) {                                   \
                (s2) = (s1); (i2) = (i1);                       \
                if ((s) < (s0)) { (s1) = (s0); (i1) = (i0); (s0) = (s); (i0) = (id); } \
                else { (s1) = (s); (i1) = (id); }               \
            } else { (s2) = (s); (i2) = (id); }                 \
        } else { (s3) = (s); (i3) = (id); }                     \
    }

// ---------------- K4: KNN2 top-4, dense tiles + triangle-inequality pruning ---
__global__ __launch_bounds__(256) void k4_knn2() {
    int bp = blockIdx.x;
    int b = bp >> 7;
    int tid = threadIdx.x, lane = tid & 31, w = tid >> 5;   // 8 warps
    __shared__ float4 buf[2048];                 // 32 KB tile
    __shared__ float  cs[8][32][4];
    __shared__ int    ci[8][32][4];

    float4 o = g_forigin[bp];                    // cluster center of the 32 queries
    float on = fmaf(o.x, o.x, fmaf(o.y, o.y, o.z * o.z));
    float o2x = -2.0f * o.x, o2y = -2.0f * o.y, o2z = -2.0f * o.z;

    float4 f = g_fpts[bp * KS + lane];           // lane = query k; f.w = |q|^2
    float m2x = -2.0f * f.x, m2y = -2.0f * f.y, m2z = -2.0f * f.z;
    float qn = f.w;
    float dqx = f.x - o.x, dqy = f.y - o.y, dqz = f.z - o.z;
    float rho = sqrtf(fmaf(dqx, dqx, fmaf(dqy, dqy, dqz * dqz))) + 1e-6f;

    float s0 = finf(), s1 = finf(), s2 = finf(), s3 = finf();
    int   i0 = 0, i1 = 0, i2 = 0, i3 = 0;

    float thrS = finf();          // survive iff s_o < thrS ; stale (larger) is safe
    int   since = 4;              // force refresh at first prune group after seed

    for (int t0 = 0; t0 < MM; t0 += 2048) {
        int n = min(2048, MM - t0);
        __syncthreads();
        for (int j = tid; j < n; j += 256) buf[j] = g_clean4[b * MM + t0 + j];
        __syncthreads();
        int chunk = (n + 7) >> 3;
        int start = w * chunk;
        int end = min(start + chunk, n);
        int r = start;

        if (t0 == 0) {
            // dense seed: first 128 refs of chunk (proven grouped-4 path)
            int seedEnd = min(start + 128, end);
#pragma unroll 2
            for (; r + 4 <= seedEnd; r += 4) {
                float4 v0 = buf[r + 0];
                float4 v1 = buf[r + 1];
                float4 v2 = buf[r + 2];
                float4 v3 = buf[r + 3];
                float sa = fmaf(v0.x, m2x, fmaf(v0.y, m2y, fmaf(v0.z, m2z, v0.w)));
                float sb = fmaf(v1.x, m2x, fmaf(v1.y, m2y, fmaf(v1.z, m2z, v1.w)));
                float sc = fmaf(v2.x, m2x, fmaf(v2.y, m2y, fmaf(v2.z, m2z, v2.w)));
                float sd = fmaf(v3.x, m2x, fmaf(v3.y, m2y, fmaf(v3.z, m2z, v3.w)));
                float m = fminf(fminf(sa, sb), fminf(sc, sd));
                if (m < s3) {
                    INS4(sa, t0 + r + 0, s0, s1, s2, s3, i0, i1, i2, i3);
                    INS4(sb, t0 + r + 1, s0, s1, s2, s3, i0, i1, i2, i3);
                    INS4(sc, t0 + r + 2, s0, s1, s2, s3, i0, i1, i2, i3);
                    INS4(sd, t0 + r + 3, s0, s1, s2, s3, i0, i1, i2, i3);
                }
            }
        }

        // pruned scan: lane-parallel center test, ballot survivors
        for (; r < end; r += 32) {
            if (since >= 4) {                     // refresh bound every 4 groups
                float d4 = sqrtf(fmaxf(s3 + qn, 0.f)) + rho;   // inf-safe
#pragma unroll
                for (int off = 16; off > 0; off >>= 1)
                    d4 = fmaxf(d4, __shfl_xor_sync(0xFFFFFFFFu, d4, off));
                thrS = fmaf(d4 * 1.0002f, d4, 1e-5f) - on;     // margin for fp rounding
                since = 0;
            }
            ++since;
            int rr = r + lane;
            bool ok = false;
            if (rr < end) {
                float4 v = buf[rr];
                float so = fmaf(v.x, o2x, fmaf(v.y, o2y, fmaf(v.z, o2z, v.w)));
                ok = so < thrS;
            }
            unsigned mk = __ballot_sync(0xFFFFFFFFu, ok);
            while (mk) {
                int bit = __ffs(mk) - 1; mk &= mk - 1;
                float4 u = buf[r + bit];          // broadcast LDS.128
                float s = fmaf(u.x, m2x, fmaf(u.y, m2y, fmaf(u.z, m2z, u.w)));
                int id = t0 + r + bit;
                INS4(s, id, s0, s1, s2, s3, i0, i1, i2, i3);
            }
        }
    }
    cs[w][lane][0] = s0; cs[w][lane][1] = s1; cs[w][lane][2] = s2; cs[w][lane][3] = s3;
    ci[w][lane][0] = i0; ci[w][lane][1] = i1; ci[w][lane][2] = i2; ci[w][lane][3] = i3;
    __syncthreads();

    if (w == 0) {
        float b0 = finf(), b1 = finf(), b2 = finf(), b3 = finf();
        int   j0 = 0, j1 = 0, j2 = 0, j3 = 0;
#pragma unroll
        for (int ww = 0; ww < 8; ++ww)
#pragma unroll
            for (int jj = 0; jj < 4; ++jj) {
                float s = cs[ww][lane][jj];
                int id = ci[ww][lane][jj];
                INS4(s, id, b0, b1, b2, b3, j0, j1, j2, j3);
            }
        float4 c0 = g_clean4[b * MM + j0];
        float4 c1 = g_clean4[b * MM + j1];
        float4 c2 = g_clean4[b * MM + j2];
        float4 c3 = g_clean4[b * MM + j3];
        float gx = (c0.x + c1.x + c2.x + c3.x) * 0.25f - f.x;
        float gy = (c0.y + c1.y + c2.y + c3.y) * 0.25f - f.y;
        float gz = (c0.z + c1.z + c2.z + c3.z) * 0.25f - f.z;
        const float* e = g_estim + (bp * KS + lane) * 3;
        float d0 = e[0] - gx, d1 = e[1] - gy, d2v = e[2] - gz;
        float err = fmaf(d0, d0, fmaf(d1, d1, d2v * d2v));
#pragma unroll
        for (int off = 16; off > 0; off >>= 1)
            err += __shfl_xor_sync(0xFFFFFFFFu, err, off);
        if (lane == 0) g_partial[bp] = err;
    }
}

// ---------------- K5: deterministic final reduce ----------------
__global__ void k5_reduce(float* __restrict__ out) {
    __shared__ float sm[512];
    int tid = threadIdx.x;
    sm[tid] = g_partial[tid];
    __syncthreads();
#pragma unroll
    for (int s = 256; s > 0; s >>= 1) {
        if (tid < s) sm[tid] += sm[tid + s];
        __syncthreads();
    }
    // loss = 0.5 * mean_{B*P*K}( sum_d (.)^2 / SIGMA ) = total * 0.5*100/16384
    if (tid == 0) out[0] = sm[0] * (50.0f / 16384.0f);
}

extern "C" void kernel_launch(void* const* d_in, const int* in_sizes, int n_in,
                              void* d_out, int out_size) {
    const float* noisy = (const float*)d_in[0];
    const float* clean = (const float*)d_in[1];
    const int*   sidx  = (const int*)d_in[2];
    const float* Wf1 = (const float*)d_in[3];
    const float* bf1 = (const float*)d_in[4];
    const float* Wf2 = (const float*)d_in[5];
    const float* bf2 = (const float*)d_in[6];
    const float* Ws1 = (const float*)d_in[7];
    const float* bs1 = (const float*)d_in[8];
    const float* Ws2 = (const float*)d_in[9];
    const float* bs2 = (const float*)d_in[10];
    const float* Ws3 = (const float*)d_in[11];
    const float* bs3 = (const float*)d_in[12];
    float* out = (float*)d_out;

    k0_pack<<<(BB * NN + 255) / 256, 256>>>(noisy, clean, sidx);
    k1_feat<<<BB * PP, 128>>>(Wf1, bf1, Wf2, bf2, Ws1, bs1);
    k2_knn1<<<BB * PP, 256>>>();
    k3_mlp<<<BB * PP * KS / 32, 256>>>(Ws1, Ws2, bs2, Ws3, bs3);
    k4_knn2<<<BB * PP, 256>>>();
    k5_reduce<<<1, 512>>>(out);
}